// round 9
// baseline (speedup 1.0000x reference)
#include <cuda_runtime.h>
#include <cuda_bf16.h>
#include <cstdint>
#include <cstddef>

#define EPS_BN 1e-5f

constexpr int Bb = 4;
constexpr int Cc = 2048;
constexpr int Rr = 512;
constexpr int Nn = 4096;   // H*W

constexpr size_t NC = (size_t)Bb * Nn * Cc;
constexpr size_t NR = (size_t)Bb * Nn * Rr;
constexpr size_t NNe = (size_t)Bb * Nn * Nn;

constexpr size_t WOF[5] = {0, 1048576, 1310720, 1572864, 1835008};
constexpr size_t WTOT = 2883584;

// ---- scratch (allocation-free) ----
__device__ __nv_bfloat16 g_XTh[NC], g_XTl[NC];
__device__ __nv_bfloat16 g_FTh[NR], g_FTl[NR];
__device__ float         g_FTf[NR];
__device__ __nv_bfloat16 g_QKh[2 * NR], g_QKl[2 * NR];  // [B][N][1024]: q|k
__device__ __nv_bfloat16 g_Vh[NR], g_Vl[NR];            // [B][R][N]
__device__ float         g_S[NNe];
__device__ __nv_bfloat16 g_Ph[NNe], g_Pl[NNe];
__device__ float         g_UT[NR];
__device__ __nv_bfloat16 g_WTh[NR], g_WTl[NR];
__device__ __nv_bfloat16 g_Wph[WTOT], g_Wpl[WTOT];
__device__ float g_alpha[5 * 2048], g_beta[5 * 2048];
__device__ float g_alqk[1024], g_beqk[1024];

// ===================== helpers =====================
__device__ __forceinline__ uint32_t smem_u32(const void* p) {
    uint32_t a;
    asm("{ .reg .u64 t; cvta.to.shared.u64 t, %1; cvt.u32.u64 %0, t; }" : "=r"(a) : "l"(p));
    return a;
}
__device__ __forceinline__ void ldsm4(uint32_t* r, uint32_t addr) {
    asm volatile("ldmatrix.sync.aligned.m8n8.x4.shared.b16 {%0,%1,%2,%3}, [%4];"
                 : "=r"(r[0]), "=r"(r[1]), "=r"(r[2]), "=r"(r[3]) : "r"(addr));
}
__device__ __forceinline__ void mma_bf16(float* c, const uint32_t* a, uint32_t b0, uint32_t b1) {
    asm volatile(
        "mma.sync.aligned.m16n8k16.row.col.f32.bf16.bf16.f32 "
        "{%0,%1,%2,%3}, {%4,%5,%6,%7}, {%8,%9}, {%0,%1,%2,%3};"
        : "+f"(c[0]), "+f"(c[1]), "+f"(c[2]), "+f"(c[3])
        : "r"(a[0]), "r"(a[1]), "r"(a[2]), "r"(a[3]), "r"(b0), "r"(b1));
}
__device__ __forceinline__ void cp16(uint32_t s, const void* g) {
    asm volatile("cp.async.cg.shared.global [%0], [%1], 16;" :: "r"(s), "l"(g));
}
__device__ __forceinline__ void cp_commit() {
    asm volatile("cp.async.commit_group;" ::: "memory");
}
__device__ __forceinline__ void cp_wait0() {
    asm volatile("cp.async.wait_group 0;" ::: "memory");
}
__device__ __forceinline__ void split1(float x, __nv_bfloat16& h, __nv_bfloat16& l) {
    h = __float2bfloat16_rn(x);
    l = __float2bfloat16_rn(x - __bfloat162float(h));
}
__device__ __forceinline__ uint32_t pack2(__nv_bfloat16 a, __nv_bfloat16 b) {
    __nv_bfloat162 p; p.x = a; p.y = b;
    return *reinterpret_cast<uint32_t*>(&p);
}

// ===================== prep =====================
struct PrepArgs {
    const float* W[5];
    const float* g[5];
    const float* b[5];
    const float* m[5];
    const float* v[5];
};

__global__ void prep_kernel(PrepArgs a) {
    const size_t wof[5] = {0, 1048576, 1310720, 1572864, 1835008};
    const int wsz[5] = {1048576, 262144, 262144, 262144, 1048576};
    int id = blockIdx.x * blockDim.x + threadIdx.x;
    if (id < 4096) {
        int L, i;
        if (id < 2048) { L = id >> 9; i = id & 511; }
        else { L = 4; i = id - 2048; }
        float al = a.g[L][i] * rsqrtf(a.v[L][i] + EPS_BN);
        float be = a.b[L][i] - a.m[L][i] * al;
        g_alpha[L * 2048 + i] = al;
        g_beta[L * 2048 + i] = be;
        if (L == 1 || L == 2) {
            g_alqk[(L - 1) * 512 + i] = al;
            g_beqk[(L - 1) * 512 + i] = be;
        }
        return;
    }
    size_t w = (size_t)id - 4096;
    if (w >= WTOT) return;
    int L = 0;
    size_t off = w;
    while (L < 4 && off >= (size_t)wsz[L]) { off -= wsz[L]; ++L; }
    float x = a.W[L][off];
    split1(x, g_Wph[wof[L] + off], g_Wpl[wof[L] + off]);
}

// ===================== feature transpose + split ============================
__global__ __launch_bounds__(256) void xt_kernel(const float* __restrict__ X) {
    __shared__ float s[32][33];
    const int c0 = blockIdx.x * 32;
    const int n0 = blockIdx.y * 32;
    const size_t zo = (size_t)blockIdx.z * Cc * Nn;
    const int tx = threadIdx.x & 31;
    const int ty = threadIdx.x >> 5;
#pragma unroll
    for (int i = 0; i < 4; ++i)
        s[ty + 8 * i][tx] = X[zo + (size_t)(c0 + ty + 8 * i) * Nn + n0 + tx];
    __syncthreads();
    const size_t zo2 = (size_t)blockIdx.z * Nn * Cc;
#pragma unroll
    for (int i = 0; i < 4; ++i) {
        float val = s[tx][ty + 8 * i];
        size_t o = zo2 + (size_t)(n0 + ty + 8 * i) * Cc + c0 + tx;
        split1(val, g_XTh[o], g_XTl[o]);
    }
}

// ===================== canonical split-bf16 GEMM ============================
// C[i,j] = sum_k A[i,k]*B[j,k];  A row stride ldA, B row stride ldB (elems).
// SCALE: 0 none, 1 row alpha[i], 2 col alpha[j]; >0 implies ReLU.
// Block tile 128x128xBK32, 128 threads (4 warps 2x2, warp tile 64x64).

template <int SCALE, bool OF32, bool OPL, bool WLO>
__global__ __launch_bounds__(128, 2) void gemm_bf16s(
    const __nv_bfloat16* __restrict__ Ah, const __nv_bfloat16* __restrict__ Al,
    const __nv_bfloat16* __restrict__ Bh, const __nv_bfloat16* __restrict__ Bl,
    float* __restrict__ Cf, __nv_bfloat16* __restrict__ Ch, __nv_bfloat16* __restrict__ Cl,
    int K, int ldA, int ldB, int ldc, long sA, long sB, long sC,
    const float* __restrict__ alpha, const float* __restrict__ beta) {
    extern __shared__ __align__(16) char smem[];
    const uint32_t su = smem_u32(smem);

    constexpr int STGB = 40960;
    constexpr int BOFF = 20480;

    const int t = threadIdx.x;
    const int lane = t & 31;
    const int wid = t >> 5;
    const int warp_m = wid >> 1;
    const int warp_n = wid & 1;
    const int bi = blockIdx.y * 128;
    const int bj = blockIdx.x * 128;
    const size_t zA = (size_t)sA * blockIdx.z;
    const size_t zB = (size_t)sB * blockIdx.z;
    const size_t zC = (size_t)sC * blockIdx.z;

    const int row = t >> 2;
    const int kc = t & 3;

    auto load_stage = [&](int stage, int k0) {
        const uint32_t sb = su + stage * STGB;
#pragma unroll
        for (int i = 0; i < 4; ++i) {
            int r = row + 32 * i;
            uint32_t so = r * 80 + kc * 16;
            cp16(sb + so,         (const char*)(Ah + zA + (size_t)(bi + r) * ldA + k0) + kc * 16);
            cp16(sb + 10240 + so, (const char*)(Al + zA + (size_t)(bi + r) * ldA + k0) + kc * 16);
            cp16(sb + BOFF + so,  (const char*)(Bh + zB + (size_t)(bj + r) * ldB + k0) + kc * 16);
            cp16(sb + 30720 + so, (const char*)(Bl + zB + (size_t)(bj + r) * ldB + k0) + kc * 16);
        }
        cp_commit();
    };

    float acc[4][8][4] = {};
    const int T = K / 32;

    load_stage(0, 0);

    const uint32_t aoff = (uint32_t)((warp_m * 64 + (lane & 15)) * 80 + (lane >> 4) * 16);
    const uint32_t boff = (uint32_t)(BOFF + (warp_n * 64 + (lane & 15)) * 80 + (lane >> 4) * 16);

    for (int tt = 0; tt < T; ++tt) {
        cp_wait0();
        __syncthreads();
        if (tt + 1 < T) load_stage((tt + 1) & 1, (tt + 1) * 32);

        const uint32_t sb = su + (tt & 1) * STGB;
        const uint32_t aHi = sb + aoff, aLo = aHi + 10240;
        const uint32_t bHi = sb + boff, bLo = bHi + 10240;

#pragma unroll
        for (int ks = 0; ks < 2; ++ks) {
            const uint32_t kof = (uint32_t)(ks * 32);
            uint32_t bh[4][4], bl[4][4];
#pragma unroll
            for (int np = 0; np < 4; ++np) {
                ldsm4(bh[np], bHi + (uint32_t)(np * 16 * 80) + kof);
                ldsm4(bl[np], bLo + (uint32_t)(np * 16 * 80) + kof);
            }
#pragma unroll
            for (int mt = 0; mt < 4; ++mt) {
                uint32_t ah[4], al_[4];
                ldsm4(ah, aHi + (uint32_t)(mt * 16 * 80) + kof);
                ldsm4(al_, aLo + (uint32_t)(mt * 16 * 80) + kof);
#pragma unroll
                for (int nt = 0; nt < 8; ++nt) {
                    const uint32_t* h = bh[nt >> 1];
                    const uint32_t* l = bl[nt >> 1];
                    mma_bf16(acc[mt][nt], ah, h[nt & 1], h[2 + (nt & 1)]);
                    mma_bf16(acc[mt][nt], al_, h[nt & 1], h[2 + (nt & 1)]);
                    mma_bf16(acc[mt][nt], ah, l[nt & 1], l[2 + (nt & 1)]);
                }
            }
        }
    }

    // ---- epilogue ----
#pragma unroll
    for (int mt = 0; mt < 4; ++mt) {
        const int m0 = bi + warp_m * 64 + mt * 16 + (lane >> 2);
        float ra0 = 1.f, rb0 = 0.f, ra1 = 1.f, rb1 = 0.f;
        if (SCALE == 1) {
            ra0 = alpha[m0]; rb0 = beta[m0];
            ra1 = alpha[m0 + 8]; rb1 = beta[m0 + 8];
        }
#pragma unroll
        for (int nt = 0; nt < 8; ++nt) {
            const int n = bj + warp_n * 64 + nt * 8 + (lane & 3) * 2;
            float v0 = acc[mt][nt][0], v1 = acc[mt][nt][1];
            float v2 = acc[mt][nt][2], v3 = acc[mt][nt][3];
            if (SCALE == 1) {
                v0 = fmaxf(fmaf(ra0, v0, rb0), 0.f); v1 = fmaxf(fmaf(ra0, v1, rb0), 0.f);
                v2 = fmaxf(fmaf(ra1, v2, rb1), 0.f); v3 = fmaxf(fmaf(ra1, v3, rb1), 0.f);
            } else if (SCALE == 2) {
                float ca0 = alpha[n], cb0 = beta[n], ca1 = alpha[n + 1], cb1 = beta[n + 1];
                v0 = fmaxf(fmaf(ca0, v0, cb0), 0.f); v1 = fmaxf(fmaf(ca1, v1, cb1), 0.f);
                v2 = fmaxf(fmaf(ca0, v2, cb0), 0.f); v3 = fmaxf(fmaf(ca1, v3, cb1), 0.f);
            }
            if (OF32) {
                *reinterpret_cast<float2*>(&Cf[zC + (size_t)m0 * ldc + n]) = make_float2(v0, v1);
                *reinterpret_cast<float2*>(&Cf[zC + (size_t)(m0 + 8) * ldc + n]) = make_float2(v2, v3);
            }
            if (OPL) {
                __nv_bfloat16 h0, l0, h1, l1;
                split1(v0, h0, l0); split1(v1, h1, l1);
                *reinterpret_cast<uint32_t*>(&Ch[zC + (size_t)m0 * ldc + n]) = pack2(h0, h1);
                if (WLO) *reinterpret_cast<uint32_t*>(&Cl[zC + (size_t)m0 * ldc + n]) = pack2(l0, l1);
                split1(v2, h0, l0); split1(v3, h1, l1);
                *reinterpret_cast<uint32_t*>(&Ch[zC + (size_t)(m0 + 8) * ldc + n]) = pack2(h0, h1);
                if (WLO) *reinterpret_cast<uint32_t*>(&Cl[zC + (size_t)(m0 + 8) * ldc + n]) = pack2(l0, l1);
            }
        }
    }
}

// ===================== softmax -> split planes ==============================
__global__ __launch_bounds__(256) void softmax_kernel() {
    const size_t ro = (size_t)blockIdx.x * Nn;
    const float* row = g_S + ro;
    const int t = threadIdx.x;
    __shared__ float redm[8], reds[8];

    float v[16];
    float m = -1e30f;
#pragma unroll
    for (int u = 0; u < 16; ++u) {
        v[u] = row[t + u * 256];
        m = fmaxf(m, v[u]);
    }
#pragma unroll
    for (int o = 16; o; o >>= 1) m = fmaxf(m, __shfl_xor_sync(0xffffffffu, m, o));
    if ((t & 31) == 0) redm[t >> 5] = m;
    __syncthreads();
    m = redm[0];
#pragma unroll
    for (int w = 1; w < 8; ++w) m = fmaxf(m, redm[w]);

    float s = 0.f;
#pragma unroll
    for (int u = 0; u < 16; ++u) {
        v[u] = __expf(v[u] - m);
        s += v[u];
    }
#pragma unroll
    for (int o = 16; o; o >>= 1) s += __shfl_xor_sync(0xffffffffu, s, o);
    if ((t & 31) == 0) reds[t >> 5] = s;
    __syncthreads();
    float tot = 0.f;
#pragma unroll
    for (int w = 0; w < 8; ++w) tot += reds[w];
    float inv = 1.0f / tot;
#pragma unroll
    for (int u = 0; u < 16; ++u) {
        float p = v[u] * inv;
        split1(p, g_Ph[ro + t + u * 256], g_Pl[ro + t + u * 256]);
    }
}

// ===================== add + split ==========================================
__global__ void add_kernel() {
    size_t i = ((size_t)blockIdx.x * blockDim.x + threadIdx.x) * 4;
    if (i >= NR) return;
    float4 f = *reinterpret_cast<const float4*>(&g_FTf[i]);
    float4 u = *reinterpret_cast<const float4*>(&g_UT[i]);
    float w0 = f.x + u.x, w1 = f.y + u.y, w2 = f.z + u.z, w3 = f.w + u.w;
    __nv_bfloat16 h0, l0, h1, l1, h2, l2, h3, l3;
    split1(w0, h0, l0); split1(w1, h1, l1); split1(w2, h2, l2); split1(w3, h3, l3);
    uint2 hp, lp;
    hp.x = pack2(h0, h1); hp.y = pack2(h2, h3);
    lp.x = pack2(l0, l1); lp.y = pack2(l2, l3);
    *reinterpret_cast<uint2*>(&g_WTh[i]) = hp;
    *reinterpret_cast<uint2*>(&g_WTl[i]) = lp;
}

// ===================== host =====================
constexpr int GSM = 2 * 40960;

extern "C" void kernel_launch(void* const* d_in, const int* in_sizes, int n_in,
                              void* d_out, int out_size) {
    const float* feature = (const float*)d_in[0];
    PrepArgs pa;
    for (int L = 0; L < 5; ++L) {
        pa.W[L] = (const float*)d_in[1 + 5 * L + 0];
        pa.g[L] = (const float*)d_in[1 + 5 * L + 1];
        pa.b[L] = (const float*)d_in[1 + 5 * L + 2];
        pa.m[L] = (const float*)d_in[1 + 5 * L + 3];
        pa.v[L] = (const float*)d_in[1 + 5 * L + 4];
    }

    __nv_bfloat16 *XTh, *XTl, *FTh, *FTl, *QKh, *QKl, *Vh, *Vl;
    __nv_bfloat16 *Ph, *Pl, *WTh, *WTl, *Wph, *Wpl;
    float *FTf, *S, *UT, *Al, *Be, *Alqk, *Beqk;
    cudaGetSymbolAddress((void**)&XTh, g_XTh); cudaGetSymbolAddress((void**)&XTl, g_XTl);
    cudaGetSymbolAddress((void**)&FTh, g_FTh); cudaGetSymbolAddress((void**)&FTl, g_FTl);
    cudaGetSymbolAddress((void**)&QKh, g_QKh); cudaGetSymbolAddress((void**)&QKl, g_QKl);
    cudaGetSymbolAddress((void**)&Vh, g_Vh);   cudaGetSymbolAddress((void**)&Vl, g_Vl);
    cudaGetSymbolAddress((void**)&Ph, g_Ph);   cudaGetSymbolAddress((void**)&Pl, g_Pl);
    cudaGetSymbolAddress((void**)&WTh, g_WTh); cudaGetSymbolAddress((void**)&WTl, g_WTl);
    cudaGetSymbolAddress((void**)&Wph, g_Wph); cudaGetSymbolAddress((void**)&Wpl, g_Wpl);
    cudaGetSymbolAddress((void**)&FTf, g_FTf); cudaGetSymbolAddress((void**)&S, g_S);
    cudaGetSymbolAddress((void**)&UT, g_UT);
    cudaGetSymbolAddress((void**)&Al, g_alpha); cudaGetSymbolAddress((void**)&Be, g_beta);
    cudaGetSymbolAddress((void**)&Alqk, g_alqk); cudaGetSymbolAddress((void**)&Beqk, g_beqk);

    cudaFuncSetAttribute(gemm_bf16s<2, true, true, true>,   cudaFuncAttributeMaxDynamicSharedMemorySize, GSM);
    cudaFuncSetAttribute(gemm_bf16s<2, false, true, true>,  cudaFuncAttributeMaxDynamicSharedMemorySize, GSM);
    cudaFuncSetAttribute(gemm_bf16s<1, false, true, true>,  cudaFuncAttributeMaxDynamicSharedMemorySize, GSM);
    cudaFuncSetAttribute(gemm_bf16s<0, true, false, false>, cudaFuncAttributeMaxDynamicSharedMemorySize, GSM);
    cudaFuncSetAttribute(gemm_bf16s<1, true, false, false>, cudaFuncAttributeMaxDynamicSharedMemorySize, GSM);

    const long sNR = (long)Nn * Rr;
    const long sNQK = (long)Nn * 1024;
    const long sNN = (long)Nn * Nn;

    // 1) prep
    prep_kernel<<<(int)((WTOT + 4096 + 255) / 256), 256>>>(pa);

    // 2) XT = transpose+split(feature)
    xt_kernel<<<dim3(Cc / 32, Nn / 32, Bb), 256>>>(feature);

    // 3) FT = cbr-col(XT x Wr)   M=4096, N=512, K=2048
    gemm_bf16s<2, true, true, true><<<dim3(4, 32, Bb), 128, GSM>>>(
        XTh, XTl, Wph + WOF[0], Wpl + WOF[0], FTf, FTh, FTl,
        Cc, Cc, Cc, Rr, (long)Nn * Cc, 0, sNR, Al + 0 * 2048, Be + 0 * 2048);

    // 4) QK = cbr-col(FT x [Wq;Wk])  M=4096, N=1024, K=512 -> [B][N][1024]
    gemm_bf16s<2, false, true, true><<<dim3(8, 32, Bb), 128, GSM>>>(
        FTh, FTl, Wph + WOF[1], Wpl + WOF[1], nullptr, QKh, QKl,
        Rr, Rr, Rr, 1024, sNR, 0, sNQK, Alqk, Beqk);

    // 5) S = Q x K^T   M=N=4096, K=512  (A = QK cols 0..511, B = QK cols 512..1023)
    gemm_bf16s<0, true, false, false><<<dim3(32, 32, Bb), 128, GSM>>>(
        QKh, QKl, QKh + 512, QKl + 512, S, nullptr, nullptr,
        Rr, 1024, 1024, Nn, sNQK, sNQK, sNN, nullptr, nullptr);

    // 6) V = cbr-row(Wv x F)   M=512, N=4096, K=512
    gemm_bf16s<1, false, true, true><<<dim3(32, 4, Bb), 128, GSM>>>(
        Wph + WOF[3], Wpl + WOF[3], FTh, FTl, nullptr, Vh, Vl,
        Rr, Rr, Rr, Nn, 0, sNR, (long)Rr * Nn, Al + 3 * 2048, Be + 3 * 2048);

    // 7) P = softmax rows -> split planes
    softmax_kernel<<<Bb * Nn, 256>>>();

    // 8) UT = P x V^T   M=4096, N=512, K=4096
    gemm_bf16s<0, true, false, false><<<dim3(4, 32, Bb), 128, GSM>>>(
        Ph, Pl, Vh, Vl, UT, nullptr, nullptr,
        Nn, Nn, Nn, Rr, sNN, (long)Rr * Nn, sNR, nullptr, nullptr);

    // 9) WT = split(FTf + UT)
    add_kernel<<<(int)((NR / 4 + 255) / 256), 256>>>();

    // 10) out = cbr-row(Wu x (F+U))   M=2048, N=4096, K=512
    gemm_bf16s<1, true, false, false><<<dim3(32, 16, Bb), 128, GSM>>>(
        Wph + WOF[4], Wpl + WOF[4], WTh, WTl, (float*)d_out, nullptr, nullptr,
        Rr, Rr, Rr, Nn, 0, sNR, (long)Cc * Nn, Al + 4 * 2048, Be + 4 * 2048);
}